// round 11
// baseline (speedup 1.0000x reference)
#include <cuda_runtime.h>
#include <cstdint>

// Conv4D with separable rank-1 kernel (K ⊗ K), VALID padding.
// input  : (8192, 8, 8, 8, 8) fp32 -> output (8192, 6, 6, 6, 6) fp32
//
// Pass 1 computed straight from coalesced LDG.128 registers using warp
// shuffles (no input staging in smem):
//   lane L, warp w, instr j  ->  plane 16w+2j+(L>>4), row (L>>1)&7, colhalf L&1
//   d4 conv: 1 shfl.bfly(1) borrow -> 5-col window -> rp[3][3]
//   d3 conv: rows rr+1, rr+2 via shfl.down 2 / 4
// T stored in smem with plane stride 48 (== 16 mod 32): store banks
// 16*hi + 6*rr + 3c all distinct -> conflict-free; pass-2 reads lanes along
// e34 (stride 1) -> conflict-free; coalesced output stores.

#define THREADS 128
#define FULLM 0xffffffffu

__global__ __launch_bounds__(THREADS, 8)
void conv4d_shfl_kernel(const float* __restrict__ in,
                        const float* __restrict__ ker,
                        float* __restrict__ out)
{
    __shared__ float s_t[64 * 48];   // T[plane][e34], stride 48: 12,288 B

    const int b   = blockIdx.x;
    const int tid = threadIdx.x;
    const int w   = tid >> 5;        // warp 0..3
    const int L   = tid & 31;        // lane

    const int hi = L >> 4;           // plane parity within pair
    const int rr = (L >> 1) & 7;     // input row 0..7
    const int c  = L & 1;            // col half 0..1

    float k[9];
#pragma unroll
    for (int i = 0; i < 9; i++) k[i] = __ldg(&ker[i]);

    const float4* gin4 = reinterpret_cast<const float4*>(in + (size_t)b * 4096);

    // ---- 8 fully-coalesced LDG.128 (4 lines per warp-op, MLP=8) ----
    float4 q[8];
#pragma unroll
    for (int j = 0; j < 8; j++)
        q[j] = __ldg(gin4 + w * 256 + j * 32 + L);

    const int plane_base = w * 16 + hi;          // plane = plane_base + 2j

    // ---- Pass 1: per plane j, conv (d3,d4) via shuffles ----
#pragma unroll
    for (int j = 0; j < 8; j++) {
        const float x0 = q[j].x, x1 = q[j].y, x2 = q[j].z, x3 = q[j].w;

        // borrow 1 float from the other col-half (col 4 for c=0, col 3 for c=1)
        const float sendv = c ? x0 : x3;
        const float recv  = __shfl_xor_sync(FULLM, sendv, 1);

        // 5-col window: cols 3c .. 3c+4
        float win[5];
        win[0] = c ? recv : x0;
        win[1] = c ? x0   : x1;
        win[2] = c ? x1   : x2;
        win[3] = c ? x2   : x3;
        win[4] = c ? x3   : recv;

        // row partials rp[kk][m]: e4 = 3c+m, kernel row kk
        float rp[3][3];
#pragma unroll
        for (int kk = 0; kk < 3; kk++)
#pragma unroll
            for (int m = 0; m < 3; m++)
                rp[kk][m] = fmaf(win[m],     k[kk * 3 + 0],
                            fmaf(win[m + 1], k[kk * 3 + 1],
                                 win[m + 2] * k[kk * 3 + 2]));

        // rows rr+1 (lane +2) and rr+2 (lane +4)
        float r1[3], r2[3];
#pragma unroll
        for (int m = 0; m < 3; m++) r1[m] = __shfl_down_sync(FULLM, rp[1][m], 2);
#pragma unroll
        for (int m = 0; m < 3; m++) r2[m] = __shfl_down_sync(FULLM, rp[2][m], 4);

        if (rr < 6) {
            const int plane = plane_base + 2 * j;
            float* tp = &s_t[plane * 48 + rr * 6 + c * 3];
            tp[0] = rp[0][0] + r1[0] + r2[0];
            tp[1] = rp[0][1] + r1[1] + r2[1];
            tp[2] = rp[0][2] + r1[2] + r2[2];
        }
    }
    __syncthreads();

    // ---- Pass 2: conv over (d1,d2). 144 units (u, h, e34), 5x5 rolling
    // window; lanes along e34 -> conflict-free LDS, coalesced stores.
    float* gout = out + (size_t)b * 1296;
#pragma unroll
    for (int base = 0; base < 144; base += THREADS) {
        const int v = tid + base;
        if (v < 144) {
            const int qg  = v / 36;          // 0..3
            const int u   = qg >> 1;         // e1 group
            const int h   = qg & 1;          // e2 group
            const int e34 = v - qg * 36;

            const float* tb = &s_t[(u * 24 + h * 3) * 48 + e34];

            float r[3][5];
#pragma unroll
            for (int jj = 0; jj < 5; jj++) {
                r[0][jj] = tb[(0 * 8 + jj) * 48];
                r[1][jj] = tb[(1 * 8 + jj) * 48];
            }

#pragma unroll
            for (int e1l = 0; e1l < 3; e1l++) {
#pragma unroll
                for (int jj = 0; jj < 5; jj++)
                    r[(e1l + 2) % 3][jj] = tb[((e1l + 2) * 8 + jj) * 48];

                float acc[3];
#pragma unroll
                for (int e2 = 0; e2 < 3; e2++) acc[e2] = 0.0f;
#pragma unroll
                for (int i = 0; i < 3; i++) {
                    const float* row = r[(e1l + i) % 3];
#pragma unroll
                    for (int jj = 0; jj < 3; jj++) {
                        const float kv = k[i * 3 + jj];
#pragma unroll
                        for (int e2 = 0; e2 < 3; e2++)
                            acc[e2] = fmaf(row[e2 + jj], kv, acc[e2]);
                    }
                }

                const int e1 = u * 3 + e1l;
#pragma unroll
                for (int e2 = 0; e2 < 3; e2++)
                    gout[e1 * 216 + (h * 3 + e2) * 36 + e34] = acc[e2];
            }
        }
    }
}

extern "C" void kernel_launch(void* const* d_in, const int* in_sizes, int n_in,
                              void* d_out, int out_size)
{
    const float* in  = (const float*)d_in[0];   // (8192,8,8,8,8) fp32
    const float* ker = (const float*)d_in[1];   // (3,3) fp32
    float*       out = (float*)d_out;           // (8192,6,6,6,6) fp32

    const int batches = in_sizes[0] / 4096;     // 8192
    conv4d_shfl_kernel<<<batches, THREADS>>>(in, ker, out);
}